// round 5
// baseline (speedup 1.0000x reference)
#include <cuda_runtime.h>
#include <cuda_bf16.h>

// PatchMatch (b=1, c=192, h=w=128); fixed: iteration_count=2, minWH=127, is_final=1.
// Persistent kernel: 1 launch for init + 28 eval steps + final, global sync via
// atomic-counter barrier. Input vectors live in smem (loaded once); ref gathered
// from L2 (the binding resource). 8 fresh candidates/step, center carried.

#define C 192
#define NF2 96          // 192 floats = 96 float2
#define H 128
#define W 128
#define NPIX (H * W)

#define NBLK 256        // persistent grid: 256 blocks x 512 thr, 2/SM guaranteed
#define NTHR 512        // 16 warps
#define PXB  64         // pixels per block (NBLK*PXB = NPIX)
#define PXW  4          // pixels per warp

__device__ float2  g_in_t2[NPIX * NF2];   // pixel-major input
__device__ float2  g_ref_t2[NPIX * NF2];  // pixel-major ref
__device__ int     g_coord[2][NPIX];      // packed y*128+x, double-buffered
__device__ float   g_score[NPIX];         // score of current coord
__device__ unsigned g_bar;                // grid barrier counter

__constant__ int c_YOFF[9] = {-1, -1, -1, 0, 0, 0, 1, 1, 1};
__constant__ int c_XOFF[9] = {-1, 0, 1, -1, 0, 1, -1, 0, 1};
__constant__ int c_DX[9]   = {0, -1, -1, 0, 0, 0, 1, 1, 0};
__constant__ int c_DY[9]   = {1, 0, 0, 1, 0, -1, 0, 0, -1};

// ---------------------------------------------------------------------------
// Both transposes in one launch (z selects map). [C][NPIX] -> [NPIX][C].
__global__ void transpose_kernel(const float* __restrict__ in0,
                                 const float* __restrict__ in1) {
    __shared__ float tile[32][33];
    const float* in = blockIdx.z ? in1 : in0;
    float* out = blockIdx.z ? (float*)g_ref_t2 : (float*)g_in_t2;
    int p0 = blockIdx.x * 32;
    int c0 = blockIdx.y * 32;
    tile[threadIdx.y][threadIdx.x] = in[(c0 + threadIdx.y) * NPIX + (p0 + threadIdx.x)];
    __syncthreads();
    out[(size_t)(p0 + threadIdx.y) * C + (c0 + threadIdx.x)] = tile[threadIdx.x][threadIdx.y];
}

__global__ void reset_bar_kernel() { g_bar = 0; }

// ---------------------------------------------------------------------------
// Fixed accumulation order everywhere -> equal coords give bit-identical sums.
__device__ __forceinline__ float dot6(float2 A0, float2 A1, float2 A2,
                                      const float2* __restrict__ r2) {
    float2 r0 = __ldg(r2), r1 = __ldg(r2 + 32), rr = __ldg(r2 + 64);
    float s;
    s = A0.x * r0.x;         s = fmaf(A0.y, r0.y, s);
    s = fmaf(A1.x, r1.x, s); s = fmaf(A1.y, r1.y, s);
    s = fmaf(A2.x, rr.x, s); s = fmaf(A2.y, rr.y, s);
    return s;
}

__device__ __forceinline__ float warpsum(float s) {
    s += __shfl_xor_sync(0xffffffffu, s, 16);
    s += __shfl_xor_sync(0xffffffffu, s, 8);
    s += __shfl_xor_sync(0xffffffffu, s, 4);
    s += __shfl_xor_sync(0xffffffffu, s, 2);
    s += __shfl_xor_sync(0xffffffffu, s, 1);
    return s;
}

__device__ __forceinline__ int reflect128(int t) {
    if (t < 0) t = -t;
    if (t > 127) t = 254 - t;
    return t;
}

// Grid barrier: counter monotonic within one launch; reset kernel zeroes it
// before each replay. Spinner bypasses L1 via volatile.
__device__ __forceinline__ void gsync(int epoch) {
    __syncthreads();
    if (threadIdx.x == 0) {
        __threadfence();
        atomicAdd(&g_bar, 1u);
        unsigned tgt = (unsigned)epoch * (unsigned)gridDim.x;
        while (*((volatile unsigned*)&g_bar) < tgt) __nanosleep(64);
    }
    __syncthreads();
}

// ---------------------------------------------------------------------------
__global__ __launch_bounds__(NTHR, 2) void pm_persistent(
    const float* __restrict__ inref_x, const float* __restrict__ inref_y,
    float* __restrict__ out, int out_size) {
    __shared__ float2 sA[PXB][NF2];   // 48 KB: this block's input vectors

    int tid = threadIdx.x;
    int wid = tid >> 5, lane = tid & 31;
    int pbase = blockIdx.x * PXB;

    // Load input vectors for our 64 pixels once (coalesced).
    for (int i = tid; i < PXB * NF2; i += NTHR)
        ((float2*)sA)[i] = g_in_t2[(size_t)pbase * NF2 + i];
    __syncthreads();

    int epoch = 0;

    // Phase 0: initial coords + scores.
#pragma unroll
    for (int i = 0; i < PXW; i++) {
        int pl = wid * PXW + i;
        int p = pbase + pl;
        int cc = ((int)inref_y[p] << 7) + (int)inref_x[p];
        float2 A0 = sA[pl][lane], A1 = sA[pl][lane + 32], A2 = sA[pl][lane + 64];
        float s = warpsum(dot6(A0, A1, A2, g_ref_t2 + (size_t)cc * NF2 + lane));
        if (lane == 0) { g_coord[0][p] = cc; g_score[p] = s; }
    }
    gsync(++epoch);

    int cur = 0;
    for (int step = 0; step < 28; step++) {
        int prop_iter = step / 14;
        int w14 = step - prop_iter * 14;
        int mode = (w14 >= 7);
        int k = 1 << (mode ? (w14 - 7) : w14);
        int m = mode ? (prop_iter % k) : 0;
        const int* cb = g_coord[cur];
        int* cn = g_coord[cur ^ 1];

        for (int i = 0; i < PXW; i++) {
            int pl = wid * PXW + i;
            int p = pbase + pl;
            int y = p >> 7, x = p & 127;
            float2 A0 = sA[pl][lane], A1 = sA[pl][lane + 32], A2 = sA[pl][lane + 64];
            int myc = __ldcg(&cb[p]);
            float sc = g_score[p];

            int cc[8];
            if (mode == 0) {
#pragma unroll
                for (int q = 0; q < 8; q++) {
                    int j = q + (q >> 2);
                    int ny = reflect128(y + k * (j / 3 - 1));
                    int nx = reflect128(x + k * (j % 3 - 1));
                    cc[q] = __ldcg(&cb[(ny << 7) + nx]);
                }
            } else {
                int x0 = myc & 127, y0 = myc >> 7;
#pragma unroll
                for (int q = 0; q < 8; q++) {
                    int j = q + (q >> 2);
                    int cx = (x0 + k * c_XOFF[j] + m * c_DX[j] + 128) & 127;
                    int cy = (y0 + k * c_YOFF[j] + m * c_DY[j] + 128) & 127;
                    cc[q] = (cy << 7) | cx;
                }
            }

            float s[8];
#pragma unroll
            for (int q = 0; q < 8; q++)
                s[q] = dot6(A0, A1, A2, g_ref_t2 + (size_t)cc[q] * NF2 + lane);

#pragma unroll
            for (int d = 16; d >= 1; d >>= 1)
#pragma unroll
                for (int q = 0; q < 8; q++)
                    s[q] += __shfl_xor_sync(0xffffffffu, s[q], d);

            // First-occurrence argmax over order [0,1,2,3, center(4), 5,6,7,8].
            float best = s[0]; int bestc = cc[0];
#pragma unroll
            for (int q = 1; q < 4; q++)
                if (s[q] > best) { best = s[q]; bestc = cc[q]; }
            if (sc > best) { best = sc; bestc = myc; }
#pragma unroll
            for (int q = 4; q < 8; q++)
                if (s[q] > best) { best = s[q]; bestc = cc[q]; }

            if (lane == 0) { cn[p] = bestc; g_score[p] = best; }
        }
        cur ^= 1;
        if (step < 27) gsync(++epoch);
    }

    // Final output (own values, no barrier needed).
#pragma unroll
    for (int i = 0; i < PXW; i++) {
        int p = pbase + wid * PXW + i;
        if (lane == 0) {
            if (p < out_size)        out[p] = (float)g_coord[cur][p];
            if (NPIX + p < out_size) out[NPIX + p] = g_score[p];
        }
    }
}

// ---------------------------------------------------------------------------
extern "C" void kernel_launch(void* const* d_in, const int* in_sizes, int n_in,
                              void* d_out, int out_size) {
    const float* input_map = (const float*)d_in[0];
    const float* ref_map   = (const float*)d_in[1];
    const float* inref_x   = (const float*)d_in[2];
    const float* inref_y   = (const float*)d_in[3];

    dim3 tb(32, 32);
    dim3 tg(NPIX / 32, C / 32, 2);
    transpose_kernel<<<tg, tb>>>(input_map, ref_map);
    reset_bar_kernel<<<1, 1>>>();
    pm_persistent<<<NBLK, NTHR>>>(inref_x, inref_y, (float*)d_out, out_size);
}

// round 6
// speedup vs baseline: 1.9258x; 1.9258x over previous
#include <cuda_runtime.h>
#include <cuda_bf16.h>

// PatchMatch (b=1, c=192, h=w=128); fixed: iteration_count=2, minWH=127, is_final=1.
// Structure: transpose(1) + prop_first(1) + prop x6 + rand7(1) + prop x7 + rand7_final(1).
// Random-search phases are pixel-local -> fused into one kernel, state in registers.

#define C 192
#define NF4 48          // 192 floats = 48 float4
#define H 128
#define W 128
#define NPIX (H * W)

__device__ float4 g_in_t4[NPIX * NF4];    // pixel-major input  [p][48]
__device__ float4 g_ref_t4[NPIX * NF4];   // pixel-major ref    [p][48]
__device__ int    g_coord[2][NPIX];       // packed y*128+x, double-buffered
__device__ float  g_score[NPIX];          // score of current coord

__constant__ int c_DX[9] = {0, -1, -1, 0, 0, 0, 1, 1, 0};
__constant__ int c_DY[9] = {1, 0, 0, 1, 0, -1, 0, 0, -1};

// ---------------------------------------------------------------------------
// Both transposes in one launch (z selects map). [C][NPIX] -> [NPIX][C].
__global__ void transpose_kernel(const float* __restrict__ in0,
                                 const float* __restrict__ in1) {
    __shared__ float tile[32][33];
    const float* in = blockIdx.z ? in1 : in0;
    float* out = blockIdx.z ? (float*)g_ref_t4 : (float*)g_in_t4;
    int p0 = blockIdx.x * 32;
    int c0 = blockIdx.y * 32;
    tile[threadIdx.y][threadIdx.x] = in[(c0 + threadIdx.y) * NPIX + (p0 + threadIdx.x)];
    __syncthreads();
    out[(size_t)(p0 + threadIdx.y) * C + (c0 + threadIdx.x)] = tile[threadIdx.x][threadIdx.y];
}

// ---------------------------------------------------------------------------
// Canonical per-lane (l in [0,16)) partial dot; identical everywhere so equal
// coords give bit-identical scores. r4 is pre-offset by l.
__device__ __forceinline__ float dot48h(float4 a0, float4 a1, float4 a2,
                                        const float4* __restrict__ r4) {
    float4 r0 = r4[0], r1 = r4[16], r2 = r4[32];
    float s;
    s = a0.x * r0.x;          s = fmaf(a0.y, r0.y, s);
    s = fmaf(a0.z, r0.z, s);  s = fmaf(a0.w, r0.w, s);
    s = fmaf(a1.x, r1.x, s);  s = fmaf(a1.y, r1.y, s);
    s = fmaf(a1.z, r1.z, s);  s = fmaf(a1.w, r1.w, s);
    s = fmaf(a2.x, r2.x, s);  s = fmaf(a2.y, r2.y, s);
    s = fmaf(a2.z, r2.z, s);  s = fmaf(a2.w, r2.w, s);
    return s;
}

__device__ __forceinline__ float halfsum(float s) {
    s += __shfl_xor_sync(0xffffffffu, s, 8);
    s += __shfl_xor_sync(0xffffffffu, s, 4);
    s += __shfl_xor_sync(0xffffffffu, s, 2);
    s += __shfl_xor_sync(0xffffffffu, s, 1);
    return s;
}

__device__ __forceinline__ int reflect128(int t) {
    if (t < 0) t = -t;
    if (t > 127) t = 254 - t;
    return t;
}

// Score a pair of candidates (one per half-warp) and fold into (best,bestc)
// in index order jA then jA+1 (strict > == first-occurrence argmax).
__device__ __forceinline__ void score_pair(float4 a0, float4 a1, float4 a2, int l,
                                           int h, int cc, float& best, int& bestc) {
    float s = halfsum(dot48h(a0, a1, a2, g_ref_t4 + (size_t)cc * NF4 + l));
    float sO = __shfl_xor_sync(0xffffffffu, s, 16);
    int   cO = __shfl_xor_sync(0xffffffffu, cc, 16);
    float s0 = h ? sO : s;  int c0 = h ? cO : cc;
    float s1 = h ? s : sO;  int c1 = h ? cc : cO;
    if (s0 > best) { best = s0; bestc = c0; }
    if (s1 > best) { best = s1; bestc = c1; }
}

// ---------------------------------------------------------------------------
// Step 0 (prop, k=1) with init fused: neighbor coords come straight from
// inref_x/y; the center score (candidate j=4) is computed as a 9th dot.
__global__ __launch_bounds__(256) void prop_first_kernel(
    const float* __restrict__ inref_x, const float* __restrict__ inref_y) {
    int warp = blockIdx.x * 8 + (threadIdx.x >> 5);
    int lane = threadIdx.x & 31;
    int h = lane >> 4, l = lane & 15;
    int p = warp;
    int y = p >> 7, x = p & 127;

    const float4* __restrict__ a4 = g_in_t4 + (size_t)p * NF4 + l;
    float4 a0 = a4[0], a1 = a4[16], a2 = a4[32];

    auto coord_at = [&](int j) {
        int ny = reflect128(y + (j / 3 - 1));
        int nx = reflect128(x + (j % 3 - 1));
        int np = (ny << 7) + nx;
        return ((int)inref_y[np] << 7) + (int)inref_x[np];
    };

    float best = -3.4e38f; int bestc = 0;
    score_pair(a0, a1, a2, l, h, coord_at(0 + h), best, bestc);
    score_pair(a0, a1, a2, l, h, coord_at(2 + h), best, bestc);
    {   // center candidate j=4 (both halves compute identical value)
        int cc4 = ((int)inref_y[p] << 7) + (int)inref_x[p];
        float s4 = halfsum(dot48h(a0, a1, a2, g_ref_t4 + (size_t)cc4 * NF4 + l));
        if (s4 > best) { best = s4; bestc = cc4; }
    }
    score_pair(a0, a1, a2, l, h, coord_at(5 + h), best, bestc);
    score_pair(a0, a1, a2, l, h, coord_at(7 + h), best, bestc);

    if (lane == 0) { g_coord[0][p] = bestc; g_score[p] = best; }
}

// ---------------------------------------------------------------------------
// Propagation step (k >= 2): neighbors' current bests, reflect boundary.
__global__ __launch_bounds__(256) void prop_kernel(int k, int cur, int nxt) {
    int warp = blockIdx.x * 8 + (threadIdx.x >> 5);
    int lane = threadIdx.x & 31;
    int h = lane >> 4, l = lane & 15;
    int p = warp;
    int y = p >> 7, x = p & 127;

    const float4* __restrict__ a4 = g_in_t4 + (size_t)p * NF4 + l;
    float4 a0 = a4[0], a1 = a4[16], a2 = a4[32];

    const int* __restrict__ cb = g_coord[cur];
    int myc = cb[p];
    float sc = g_score[p];

    auto coord_at = [&](int j) {
        int ny = reflect128(y + k * (j / 3 - 1));
        int nx = reflect128(x + k * (j % 3 - 1));
        return cb[(ny << 7) + nx];
    };

    float best = -3.4e38f; int bestc = 0;
    score_pair(a0, a1, a2, l, h, coord_at(0 + h), best, bestc);
    score_pair(a0, a1, a2, l, h, coord_at(2 + h), best, bestc);
    if (sc > best) { best = sc; bestc = myc; }
    score_pair(a0, a1, a2, l, h, coord_at(5 + h), best, bestc);
    score_pair(a0, a1, a2, l, h, coord_at(7 + h), best, bestc);

    if (lane == 0) { g_coord[nxt][p] = bestc; g_score[p] = best; }
}

// ---------------------------------------------------------------------------
// Fused random-search phase: 7 steps (k=1..64), all pixel-local. State in
// registers; in-place coord update. FINAL=1 writes the output instead.
template <int FINAL>
__global__ __launch_bounds__(256) void rand7_kernel(int prop_iter, int cur,
                                                    float* __restrict__ out,
                                                    int out_size) {
    int warp = blockIdx.x * 8 + (threadIdx.x >> 5);
    int lane = threadIdx.x & 31;
    int h = lane >> 4, l = lane & 15;
    int p = warp;

    const float4* __restrict__ a4 = g_in_t4 + (size_t)p * NF4 + l;
    float4 a0 = a4[0], a1 = a4[16], a2 = a4[32];

    int myc = g_coord[cur][p];
    float sc = g_score[p];

#pragma unroll
    for (int t = 0; t < 7; t++) {
        const int k = 1 << t;
        const int m = prop_iter & (k - 1);       // prop_iter % k
        int x0 = myc & 127, y0 = myc >> 7;

        auto coord_at = [&](int j) {
            int cx = (x0 + k * (j % 3 - 1) + m * c_DX[j] + 128) & 127;
            int cy = (y0 + k * (j / 3 - 1) + m * c_DY[j] + 128) & 127;
            return (cy << 7) | cx;
        };

        float best = -3.4e38f; int bestc = 0;
        score_pair(a0, a1, a2, l, h, coord_at(0 + h), best, bestc);
        score_pair(a0, a1, a2, l, h, coord_at(2 + h), best, bestc);
        if (sc > best) { best = sc; bestc = myc; }
        score_pair(a0, a1, a2, l, h, coord_at(5 + h), best, bestc);
        score_pair(a0, a1, a2, l, h, coord_at(7 + h), best, bestc);
        myc = bestc; sc = best;
    }

    if (FINAL) {
        if (lane == 0) {
            if (p < out_size)        out[p] = (float)myc;
            if (NPIX + p < out_size) out[NPIX + p] = sc;
        }
    } else {
        if (lane == 0) { g_coord[cur][p] = myc; g_score[p] = sc; }
    }
}

// ---------------------------------------------------------------------------
extern "C" void kernel_launch(void* const* d_in, const int* in_sizes, int n_in,
                              void* d_out, int out_size) {
    const float* input_map = (const float*)d_in[0];
    const float* ref_map   = (const float*)d_in[1];
    const float* inref_x   = (const float*)d_in[2];
    const float* inref_y   = (const float*)d_in[3];

    dim3 tb(32, 32);
    dim3 tg(NPIX / 32, C / 32, 2);
    transpose_kernel<<<tg, tb>>>(input_map, ref_map);

    const int grid = NPIX / 8;   // warp per pixel, 8 warps per 256-thread block

    // Iteration 0: prop k=1 (init fused), prop k=2..64, rand phase (m=0).
    prop_first_kernel<<<grid, 256>>>(inref_x, inref_y);
    int cur = 0;
    for (int k = 2; k <= 127; k *= 2) {
        prop_kernel<<<grid, 256>>>(k, cur, cur ^ 1);
        cur ^= 1;
    }
    rand7_kernel<0><<<grid, 256>>>(0, cur, nullptr, 0);

    // Iteration 1: prop k=1..64, rand phase (m = 1 % k) + final output.
    for (int k = 1; k <= 127; k *= 2) {
        prop_kernel<<<grid, 256>>>(k, cur, cur ^ 1);
        cur ^= 1;
    }
    rand7_kernel<1><<<grid, 256>>>(1, cur, (float*)d_out, out_size);
}

// round 7
// speedup vs baseline: 2.0651x; 1.0724x over previous
#include <cuda_runtime.h>
#include <cuda_bf16.h>

// PatchMatch (b=1, c=192, h=w=128); fixed: iteration_count=2, minWH=127, is_final=1.
// Launch plan (15 kernels, PDL overlap on all eval->eval edges):
//   transpose | prop_first(k=1,init) prop(2..32)x5 rand7A(prop64+7 rand)
//             | prop(1..32)x6 rand7B(prop64+7 rand+output)

#define C 192
#define NF4 48          // 192 floats = 48 float4
#define H 128
#define W 128
#define NPIX (H * W)

#define PDL_SIGNAL() asm volatile("griddepcontrol.launch_dependents;")
#define PDL_WAIT()   asm volatile("griddepcontrol.wait;" ::: "memory")

__device__ float4 g_in_t4[NPIX * NF4];    // pixel-major input  [p][48]
__device__ float4 g_ref_t4[NPIX * NF4];   // pixel-major ref    [p][48]
__device__ int    g_coord[2][NPIX];       // packed y*128+x, double-buffered
__device__ float  g_score[NPIX];          // score of current coord

__constant__ int c_DX[9] = {0, -1, -1, 0, 0, 0, 1, 1, 0};
__constant__ int c_DY[9] = {1, 0, 0, 1, 0, -1, 0, 0, -1};

// ---------------------------------------------------------------------------
// Both transposes in one launch (z selects map). [C][NPIX] -> [NPIX][C].
__global__ void transpose_kernel(const float* __restrict__ in0,
                                 const float* __restrict__ in1) {
    __shared__ float tile[32][33];
    const float* in = blockIdx.z ? in1 : in0;
    float* out = blockIdx.z ? (float*)g_ref_t4 : (float*)g_in_t4;
    int p0 = blockIdx.x * 32;
    int c0 = blockIdx.y * 32;
    tile[threadIdx.y][threadIdx.x] = in[(c0 + threadIdx.y) * NPIX + (p0 + threadIdx.x)];
    __syncthreads();
    out[(size_t)(p0 + threadIdx.y) * C + (c0 + threadIdx.x)] = tile[threadIdx.x][threadIdx.y];
}

// ---------------------------------------------------------------------------
// Canonical per-lane (l in [0,16)) partial dot; identical everywhere so equal
// coords give bit-identical scores. r4 is pre-offset by l.
__device__ __forceinline__ float dot48h(float4 a0, float4 a1, float4 a2,
                                        const float4* __restrict__ r4) {
    float4 r0 = r4[0], r1 = r4[16], r2 = r4[32];
    float s;
    s = a0.x * r0.x;          s = fmaf(a0.y, r0.y, s);
    s = fmaf(a0.z, r0.z, s);  s = fmaf(a0.w, r0.w, s);
    s = fmaf(a1.x, r1.x, s);  s = fmaf(a1.y, r1.y, s);
    s = fmaf(a1.z, r1.z, s);  s = fmaf(a1.w, r1.w, s);
    s = fmaf(a2.x, r2.x, s);  s = fmaf(a2.y, r2.y, s);
    s = fmaf(a2.z, r2.z, s);  s = fmaf(a2.w, r2.w, s);
    return s;
}

__device__ __forceinline__ float halfsum(float s) {
    s += __shfl_xor_sync(0xffffffffu, s, 8);
    s += __shfl_xor_sync(0xffffffffu, s, 4);
    s += __shfl_xor_sync(0xffffffffu, s, 2);
    s += __shfl_xor_sync(0xffffffffu, s, 1);
    return s;
}

__device__ __forceinline__ int reflect128(int t) {
    if (t < 0) t = -t;
    if (t > 127) t = 254 - t;
    return t;
}

// Score a pair of candidates (one per half-warp) and fold into (best,bestc)
// in index order jA then jA+1 (strict > == first-occurrence argmax).
__device__ __forceinline__ void score_pair(float4 a0, float4 a1, float4 a2, int l,
                                           int h, int cc, float& best, int& bestc) {
    float s = halfsum(dot48h(a0, a1, a2, g_ref_t4 + (size_t)cc * NF4 + l));
    float sO = __shfl_xor_sync(0xffffffffu, s, 16);
    int   cO = __shfl_xor_sync(0xffffffffu, cc, 16);
    float s0 = h ? sO : s;  int c0 = h ? cO : cc;
    float s1 = h ? s : sO;  int c1 = h ? cc : cO;
    if (s0 > best) { best = s0; bestc = c0; }
    if (s1 > best) { best = s1; bestc = c1; }
}

// One propagation step given preloaded input regs; returns updated (myc, sc).
__device__ __forceinline__ void prop_step(float4 a0, float4 a1, float4 a2,
                                          int l, int h, int p, int k,
                                          const int* __restrict__ cb,
                                          int& myc, float& sc) {
    int y = p >> 7, x = p & 127;
    auto coord_at = [&](int j) {
        int ny = reflect128(y + k * (j / 3 - 1));
        int nx = reflect128(x + k * (j % 3 - 1));
        return cb[(ny << 7) + nx];
    };
    float best = -3.4e38f; int bestc = 0;
    score_pair(a0, a1, a2, l, h, coord_at(0 + h), best, bestc);
    score_pair(a0, a1, a2, l, h, coord_at(2 + h), best, bestc);
    if (sc > best) { best = sc; bestc = myc; }
    score_pair(a0, a1, a2, l, h, coord_at(5 + h), best, bestc);
    score_pair(a0, a1, a2, l, h, coord_at(7 + h), best, bestc);
    myc = bestc; sc = best;
}

// ---------------------------------------------------------------------------
// Step 0 (prop, k=1) with init fused: neighbor coords straight from inref_x/y;
// center score computed as a 9th dot. Everything after PDL wait (reads
// transpose output).
__global__ __launch_bounds__(256) void prop_first_kernel(
    const float* __restrict__ inref_x, const float* __restrict__ inref_y) {
    PDL_SIGNAL();
    PDL_WAIT();
    int warp = blockIdx.x * 8 + (threadIdx.x >> 5);
    int lane = threadIdx.x & 31;
    int h = lane >> 4, l = lane & 15;
    int p = warp;
    int y = p >> 7, x = p & 127;

    const float4* __restrict__ a4 = g_in_t4 + (size_t)p * NF4 + l;
    float4 a0 = a4[0], a1 = a4[16], a2 = a4[32];

    auto coord_at = [&](int j) {
        int ny = reflect128(y + (j / 3 - 1));
        int nx = reflect128(x + (j % 3 - 1));
        int np = (ny << 7) + nx;
        return ((int)inref_y[np] << 7) + (int)inref_x[np];
    };

    float best = -3.4e38f; int bestc = 0;
    score_pair(a0, a1, a2, l, h, coord_at(0 + h), best, bestc);
    score_pair(a0, a1, a2, l, h, coord_at(2 + h), best, bestc);
    {   // center candidate j=4
        int cc4 = ((int)inref_y[p] << 7) + (int)inref_x[p];
        float s4 = halfsum(dot48h(a0, a1, a2, g_ref_t4 + (size_t)cc4 * NF4 + l));
        if (s4 > best) { best = s4; bestc = cc4; }
    }
    score_pair(a0, a1, a2, l, h, coord_at(5 + h), best, bestc);
    score_pair(a0, a1, a2, l, h, coord_at(7 + h), best, bestc);

    if (lane == 0) { g_coord[0][p] = bestc; g_score[p] = best; }
}

// ---------------------------------------------------------------------------
// Propagation step (k >= 2). Early phase: input loads (static data) overlap
// the predecessor's tail; wait gates the coord/score reads.
__global__ __launch_bounds__(256) void prop_kernel(int k, int cur, int nxt) {
    PDL_SIGNAL();
    int warp = blockIdx.x * 8 + (threadIdx.x >> 5);
    int lane = threadIdx.x & 31;
    int h = lane >> 4, l = lane & 15;
    int p = warp;

    const float4* __restrict__ a4 = g_in_t4 + (size_t)p * NF4 + l;
    float4 a0 = a4[0], a1 = a4[16], a2 = a4[32];

    PDL_WAIT();
    const int* __restrict__ cb = g_coord[cur];
    int myc = cb[p];
    float sc = g_score[p];

    prop_step(a0, a1, a2, l, h, p, k, cb, myc, sc);

    if (lane == 0) { g_coord[nxt][p] = myc; g_score[p] = sc; }
}

// ---------------------------------------------------------------------------
// Fused: one prop step (k=64) + 7 random-search steps (k=1..64), state in
// registers. Writes the OTHER coord buffer (concurrent readers of cur exist).
// FINAL=1 writes the kernel output instead.
template <int FINAL>
__global__ __launch_bounds__(256) void rand7_kernel(int prop_iter, int cur,
                                                    float* __restrict__ out,
                                                    int out_size) {
    PDL_SIGNAL();
    int warp = blockIdx.x * 8 + (threadIdx.x >> 5);
    int lane = threadIdx.x & 31;
    int h = lane >> 4, l = lane & 15;
    int p = warp;

    const float4* __restrict__ a4 = g_in_t4 + (size_t)p * NF4 + l;
    float4 a0 = a4[0], a1 = a4[16], a2 = a4[32];

    PDL_WAIT();
    const int* __restrict__ cb = g_coord[cur];
    int myc = cb[p];
    float sc = g_score[p];

    // trailing propagation step of this half-iteration (k = 64)
    prop_step(a0, a1, a2, l, h, p, 64, cb, myc, sc);

    // 7 random-search steps, pixel-local
#pragma unroll
    for (int t = 0; t < 7; t++) {
        const int k = 1 << t;
        const int m = prop_iter & (k - 1);       // prop_iter % k
        int x0 = myc & 127, y0 = myc >> 7;

        auto coord_at = [&](int j) {
            int cx = (x0 + k * (j % 3 - 1) + m * c_DX[j] + 128) & 127;
            int cy = (y0 + k * (j / 3 - 1) + m * c_DY[j] + 128) & 127;
            return (cy << 7) | cx;
        };

        float best = -3.4e38f; int bestc = 0;
        score_pair(a0, a1, a2, l, h, coord_at(0 + h), best, bestc);
        score_pair(a0, a1, a2, l, h, coord_at(2 + h), best, bestc);
        if (sc > best) { best = sc; bestc = myc; }
        score_pair(a0, a1, a2, l, h, coord_at(5 + h), best, bestc);
        score_pair(a0, a1, a2, l, h, coord_at(7 + h), best, bestc);
        myc = bestc; sc = best;
    }

    if (FINAL) {
        if (lane == 0) {
            if (p < out_size)        out[p] = (float)myc;
            if (NPIX + p < out_size) out[NPIX + p] = sc;
        }
    } else {
        if (lane == 0) { g_coord[cur ^ 1][p] = myc; g_score[p] = sc; }
    }
}

// ---------------------------------------------------------------------------
template <typename K, typename... Args>
static void pdl_launch(K kern, dim3 g, dim3 b, Args... args) {
    cudaLaunchConfig_t cfg = {};
    cfg.gridDim = g;
    cfg.blockDim = b;
    cfg.stream = 0;   // legacy default stream (same as <<<>>>)
    cudaLaunchAttribute attr[1];
    attr[0].id = cudaLaunchAttributeProgrammaticStreamSerialization;
    attr[0].val.programmaticStreamSerializationAllowed = 1;
    cfg.attrs = attr;
    cfg.numAttrs = 1;
    cudaLaunchKernelEx(&cfg, kern, args...);
}

extern "C" void kernel_launch(void* const* d_in, const int* in_sizes, int n_in,
                              void* d_out, int out_size) {
    const float* input_map = (const float*)d_in[0];
    const float* ref_map   = (const float*)d_in[1];
    const float* inref_x   = (const float*)d_in[2];
    const float* inref_y   = (const float*)d_in[3];

    dim3 tb(32, 32);
    dim3 tg(NPIX / 32, C / 32, 2);
    transpose_kernel<<<tg, tb>>>(input_map, ref_map);

    const dim3 grid(NPIX / 8);   // warp per pixel, 8 warps per 256-thread block
    const dim3 blk(256);

    // Iteration 0: prop k=1 (init fused), k=2..32, then rand7A (prop64 + rand).
    pdl_launch(prop_first_kernel, grid, blk, inref_x, inref_y);
    int cur = 0;
    for (int k = 2; k <= 32; k *= 2) {
        pdl_launch(prop_kernel, grid, blk, k, cur, cur ^ 1);
        cur ^= 1;
    }
    pdl_launch(rand7_kernel<0>, grid, blk, 0, cur, (float*)nullptr, 0);
    cur ^= 1;

    // Iteration 1: prop k=1..32, then rand7B (prop64 + rand + output).
    for (int k = 1; k <= 32; k *= 2) {
        pdl_launch(prop_kernel, grid, blk, k, cur, cur ^ 1);
        cur ^= 1;
    }
    pdl_launch(rand7_kernel<1>, grid, blk, 1, cur, (float*)d_out, out_size);
}

// round 8
// speedup vs baseline: 2.0660x; 1.0004x over previous
#include <cuda_runtime.h>
#include <cuda_bf16.h>

// PatchMatch (b=1, c=192, h=w=128); fixed: iteration_count=2, minWH=127, is_final=1.
// Launch plan (15 kernels, PDL overlap on all eval->eval edges):
//   transpose | prop_first(k=1,init) prop(2..32)x5 rand7A(prop64+7 rand)
//             | prop(1..32)x6 rand7B(prop64+7 rand+output)

#define C 192
#define NF4 48          // 192 floats = 48 float4
#define H 128
#define W 128
#define NPIX (H * W)

#define PDL_SIGNAL() asm volatile("griddepcontrol.launch_dependents;")
#define PDL_WAIT()   asm volatile("griddepcontrol.wait;" ::: "memory")

__device__ float4 g_in_t4[NPIX * NF4];    // pixel-major input  [p][48]
__device__ float4 g_ref_t4[NPIX * NF4];   // pixel-major ref    [p][48]
__device__ int    g_coord[2][NPIX];       // packed y*128+x, double-buffered
__device__ float  g_score[NPIX];          // score of current coord

__constant__ int c_DX[9] = {0, -1, -1, 0, 0, 0, 1, 1, 0};
__constant__ int c_DY[9] = {1, 0, 0, 1, 0, -1, 0, 0, -1};

// ---------------------------------------------------------------------------
// Both transposes in one launch (z selects map). [C][NPIX] -> [NPIX][C].
__global__ void transpose_kernel(const float* __restrict__ in0,
                                 const float* __restrict__ in1) {
    __shared__ float tile[32][33];
    const float* in = blockIdx.z ? in1 : in0;
    float* out = blockIdx.z ? (float*)g_ref_t4 : (float*)g_in_t4;
    int p0 = blockIdx.x * 32;
    int c0 = blockIdx.y * 32;
    tile[threadIdx.y][threadIdx.x] = in[(c0 + threadIdx.y) * NPIX + (p0 + threadIdx.x)];
    __syncthreads();
    out[(size_t)(p0 + threadIdx.y) * C + (c0 + threadIdx.x)] = tile[threadIdx.x][threadIdx.y];
}

// ---------------------------------------------------------------------------
// Canonical per-lane (l in [0,16)) partial dot; identical everywhere so equal
// coords give bit-identical scores. r4 is pre-offset by l.
__device__ __forceinline__ float dot48h(float4 a0, float4 a1, float4 a2,
                                        const float4* __restrict__ r4) {
    float4 r0 = r4[0], r1 = r4[16], r2 = r4[32];
    float s;
    s = a0.x * r0.x;          s = fmaf(a0.y, r0.y, s);
    s = fmaf(a0.z, r0.z, s);  s = fmaf(a0.w, r0.w, s);
    s = fmaf(a1.x, r1.x, s);  s = fmaf(a1.y, r1.y, s);
    s = fmaf(a1.z, r1.z, s);  s = fmaf(a1.w, r1.w, s);
    s = fmaf(a2.x, r2.x, s);  s = fmaf(a2.y, r2.y, s);
    s = fmaf(a2.z, r2.z, s);  s = fmaf(a2.w, r2.w, s);
    return s;
}

__device__ __forceinline__ float halfsum(float s) {
    s += __shfl_xor_sync(0xffffffffu, s, 8);
    s += __shfl_xor_sync(0xffffffffu, s, 4);
    s += __shfl_xor_sync(0xffffffffu, s, 2);
    s += __shfl_xor_sync(0xffffffffu, s, 1);
    return s;
}

__device__ __forceinline__ int reflect128(int t) {
    if (t < 0) t = -t;
    if (t > 127) t = 254 - t;
    return t;
}

// Score a pair of candidates (one per half-warp) and fold into (best,bestc)
// in index order jA then jA+1 (strict > == first-occurrence argmax).
__device__ __forceinline__ void score_pair(float4 a0, float4 a1, float4 a2, int l,
                                           int h, int cc, float& best, int& bestc) {
    float s = halfsum(dot48h(a0, a1, a2, g_ref_t4 + (size_t)cc * NF4 + l));
    float sO = __shfl_xor_sync(0xffffffffu, s, 16);
    int   cO = __shfl_xor_sync(0xffffffffu, cc, 16);
    float s0 = h ? sO : s;  int c0 = h ? cO : cc;
    float s1 = h ? s : sO;  int c1 = h ? cc : cO;
    if (s0 > best) { best = s0; bestc = c0; }
    if (s1 > best) { best = s1; bestc = c1; }
}

// One propagation step given preloaded input regs; returns updated (myc, sc).
__device__ __forceinline__ void prop_step(float4 a0, float4 a1, float4 a2,
                                          int l, int h, int p, int k,
                                          const int* __restrict__ cb,
                                          int& myc, float& sc) {
    int y = p >> 7, x = p & 127;
    auto coord_at = [&](int j) {
        int ny = reflect128(y + k * (j / 3 - 1));
        int nx = reflect128(x + k * (j % 3 - 1));
        return cb[(ny << 7) + nx];
    };
    float best = -3.4e38f; int bestc = 0;
    score_pair(a0, a1, a2, l, h, coord_at(0 + h), best, bestc);
    score_pair(a0, a1, a2, l, h, coord_at(2 + h), best, bestc);
    if (sc > best) { best = sc; bestc = myc; }
    score_pair(a0, a1, a2, l, h, coord_at(5 + h), best, bestc);
    score_pair(a0, a1, a2, l, h, coord_at(7 + h), best, bestc);
    myc = bestc; sc = best;
}

// ---------------------------------------------------------------------------
// Step 0 (prop, k=1) with init fused: neighbor coords straight from inref_x/y;
// center score computed as a 9th dot. Everything after PDL wait (reads
// transpose output).
__global__ __launch_bounds__(256) void prop_first_kernel(
    const float* __restrict__ inref_x, const float* __restrict__ inref_y) {
    PDL_SIGNAL();
    PDL_WAIT();
    int warp = blockIdx.x * 8 + (threadIdx.x >> 5);
    int lane = threadIdx.x & 31;
    int h = lane >> 4, l = lane & 15;
    int p = warp;
    int y = p >> 7, x = p & 127;

    const float4* __restrict__ a4 = g_in_t4 + (size_t)p * NF4 + l;
    float4 a0 = a4[0], a1 = a4[16], a2 = a4[32];

    auto coord_at = [&](int j) {
        int ny = reflect128(y + (j / 3 - 1));
        int nx = reflect128(x + (j % 3 - 1));
        int np = (ny << 7) + nx;
        return ((int)inref_y[np] << 7) + (int)inref_x[np];
    };

    float best = -3.4e38f; int bestc = 0;
    score_pair(a0, a1, a2, l, h, coord_at(0 + h), best, bestc);
    score_pair(a0, a1, a2, l, h, coord_at(2 + h), best, bestc);
    {   // center candidate j=4
        int cc4 = ((int)inref_y[p] << 7) + (int)inref_x[p];
        float s4 = halfsum(dot48h(a0, a1, a2, g_ref_t4 + (size_t)cc4 * NF4 + l));
        if (s4 > best) { best = s4; bestc = cc4; }
    }
    score_pair(a0, a1, a2, l, h, coord_at(5 + h), best, bestc);
    score_pair(a0, a1, a2, l, h, coord_at(7 + h), best, bestc);

    if (lane == 0) { g_coord[0][p] = bestc; g_score[p] = best; }
}

// ---------------------------------------------------------------------------
// Propagation step (k >= 2). Early phase: input loads (static data) overlap
// the predecessor's tail; wait gates the coord/score reads.
__global__ __launch_bounds__(256) void prop_kernel(int k, int cur, int nxt) {
    PDL_SIGNAL();
    int warp = blockIdx.x * 8 + (threadIdx.x >> 5);
    int lane = threadIdx.x & 31;
    int h = lane >> 4, l = lane & 15;
    int p = warp;

    const float4* __restrict__ a4 = g_in_t4 + (size_t)p * NF4 + l;
    float4 a0 = a4[0], a1 = a4[16], a2 = a4[32];

    PDL_WAIT();
    const int* __restrict__ cb = g_coord[cur];
    int myc = cb[p];
    float sc = g_score[p];

    prop_step(a0, a1, a2, l, h, p, k, cb, myc, sc);

    if (lane == 0) { g_coord[nxt][p] = myc; g_score[p] = sc; }
}

// ---------------------------------------------------------------------------
// Fused: one prop step (k=64) + 7 random-search steps (k=1..64), state in
// registers. Writes the OTHER coord buffer (concurrent readers of cur exist).
// FINAL=1 writes the kernel output instead.
template <int FINAL>
__global__ __launch_bounds__(256) void rand7_kernel(int prop_iter, int cur,
                                                    float* __restrict__ out,
                                                    int out_size) {
    PDL_SIGNAL();
    int warp = blockIdx.x * 8 + (threadIdx.x >> 5);
    int lane = threadIdx.x & 31;
    int h = lane >> 4, l = lane & 15;
    int p = warp;

    const float4* __restrict__ a4 = g_in_t4 + (size_t)p * NF4 + l;
    float4 a0 = a4[0], a1 = a4[16], a2 = a4[32];

    PDL_WAIT();
    const int* __restrict__ cb = g_coord[cur];
    int myc = cb[p];
    float sc = g_score[p];

    // trailing propagation step of this half-iteration (k = 64)
    prop_step(a0, a1, a2, l, h, p, 64, cb, myc, sc);

    // 7 random-search steps, pixel-local
#pragma unroll
    for (int t = 0; t < 7; t++) {
        const int k = 1 << t;
        const int m = prop_iter & (k - 1);       // prop_iter % k
        int x0 = myc & 127, y0 = myc >> 7;

        auto coord_at = [&](int j) {
            int cx = (x0 + k * (j % 3 - 1) + m * c_DX[j] + 128) & 127;
            int cy = (y0 + k * (j / 3 - 1) + m * c_DY[j] + 128) & 127;
            return (cy << 7) | cx;
        };

        float best = -3.4e38f; int bestc = 0;
        score_pair(a0, a1, a2, l, h, coord_at(0 + h), best, bestc);
        score_pair(a0, a1, a2, l, h, coord_at(2 + h), best, bestc);
        if (sc > best) { best = sc; bestc = myc; }
        score_pair(a0, a1, a2, l, h, coord_at(5 + h), best, bestc);
        score_pair(a0, a1, a2, l, h, coord_at(7 + h), best, bestc);
        myc = bestc; sc = best;
    }

    if (FINAL) {
        if (lane == 0) {
            if (p < out_size)        out[p] = (float)myc;
            if (NPIX + p < out_size) out[NPIX + p] = sc;
        }
    } else {
        if (lane == 0) { g_coord[cur ^ 1][p] = myc; g_score[p] = sc; }
    }
}

// ---------------------------------------------------------------------------
template <typename K, typename... Args>
static void pdl_launch(K kern, dim3 g, dim3 b, Args... args) {
    cudaLaunchConfig_t cfg = {};
    cfg.gridDim = g;
    cfg.blockDim = b;
    cfg.stream = 0;   // legacy default stream (same as <<<>>>)
    cudaLaunchAttribute attr[1];
    attr[0].id = cudaLaunchAttributeProgrammaticStreamSerialization;
    attr[0].val.programmaticStreamSerializationAllowed = 1;
    cfg.attrs = attr;
    cfg.numAttrs = 1;
    cudaLaunchKernelEx(&cfg, kern, args...);
}

extern "C" void kernel_launch(void* const* d_in, const int* in_sizes, int n_in,
                              void* d_out, int out_size) {
    const float* input_map = (const float*)d_in[0];
    const float* ref_map   = (const float*)d_in[1];
    const float* inref_x   = (const float*)d_in[2];
    const float* inref_y   = (const float*)d_in[3];

    dim3 tb(32, 32);
    dim3 tg(NPIX / 32, C / 32, 2);
    transpose_kernel<<<tg, tb>>>(input_map, ref_map);

    const dim3 grid(NPIX / 8);   // warp per pixel, 8 warps per 256-thread block
    const dim3 blk(256);

    // Iteration 0: prop k=1 (init fused), k=2..32, then rand7A (prop64 + rand).
    pdl_launch(prop_first_kernel, grid, blk, inref_x, inref_y);
    int cur = 0;
    for (int k = 2; k <= 32; k *= 2) {
        pdl_launch(prop_kernel, grid, blk, k, cur, cur ^ 1);
        cur ^= 1;
    }
    pdl_launch(rand7_kernel<0>, grid, blk, 0, cur, (float*)nullptr, 0);
    cur ^= 1;

    // Iteration 1: prop k=1..32, then rand7B (prop64 + rand + output).
    for (int k = 1; k <= 32; k *= 2) {
        pdl_launch(prop_kernel, grid, blk, k, cur, cur ^ 1);
        cur ^= 1;
    }
    pdl_launch(rand7_kernel<1>, grid, blk, 1, cur, (float*)d_out, out_size);
}

// round 9
// speedup vs baseline: 2.0684x; 1.0012x over previous
#include <cuda_runtime.h>
#include <cuda_bf16.h>

// PatchMatch (b=1, c=192, h=w=128); fixed: iteration_count=2, minWH=127, is_final=1.
// Launch plan (15 kernels, PDL overlap on all eval->eval edges):
//   transpose | prop_first(k=1,init) prop(2..32)x5 rand7A(prop64+7 rand)
//             | prop(1..32)x6 rand7B(prop64+7 rand+output)

#define C 192
#define NF4 48          // 192 floats = 48 float4
#define H 128
#define W 128
#define NPIX (H * W)

#define PDL_SIGNAL() asm volatile("griddepcontrol.launch_dependents;")
#define PDL_WAIT()   asm volatile("griddepcontrol.wait;" ::: "memory")

__device__ float4 g_in_t4[NPIX * NF4];    // pixel-major input  [p][48]
__device__ float4 g_ref_t4[NPIX * NF4];   // pixel-major ref    [p][48]
__device__ int    g_coord[2][NPIX];       // packed y*128+x, double-buffered
__device__ float  g_score[NPIX];          // score of current coord

__constant__ int c_DX[9] = {0, -1, -1, 0, 0, 0, 1, 1, 0};
__constant__ int c_DY[9] = {1, 0, 0, 1, 0, -1, 0, 0, -1};

// ---------------------------------------------------------------------------
// Both transposes in one launch (z selects map). [C][NPIX] -> [NPIX][C].
__global__ void transpose_kernel(const float* __restrict__ in0,
                                 const float* __restrict__ in1) {
    __shared__ float tile[32][33];
    const float* in = blockIdx.z ? in1 : in0;
    float* out = blockIdx.z ? (float*)g_ref_t4 : (float*)g_in_t4;
    int p0 = blockIdx.x * 32;
    int c0 = blockIdx.y * 32;
    tile[threadIdx.y][threadIdx.x] = in[(c0 + threadIdx.y) * NPIX + (p0 + threadIdx.x)];
    __syncthreads();
    out[(size_t)(p0 + threadIdx.y) * C + (c0 + threadIdx.x)] = tile[threadIdx.x][threadIdx.y];
}

// ---------------------------------------------------------------------------
// Canonical per-lane (l in [0,16)) partial dot; identical everywhere so equal
// coords give bit-identical scores. r4 is pre-offset by l.
__device__ __forceinline__ float dot48h(float4 a0, float4 a1, float4 a2,
                                        const float4* __restrict__ r4) {
    float4 r0 = r4[0], r1 = r4[16], r2 = r4[32];
    float s;
    s = a0.x * r0.x;          s = fmaf(a0.y, r0.y, s);
    s = fmaf(a0.z, r0.z, s);  s = fmaf(a0.w, r0.w, s);
    s = fmaf(a1.x, r1.x, s);  s = fmaf(a1.y, r1.y, s);
    s = fmaf(a1.z, r1.z, s);  s = fmaf(a1.w, r1.w, s);
    s = fmaf(a2.x, r2.x, s);  s = fmaf(a2.y, r2.y, s);
    s = fmaf(a2.z, r2.z, s);  s = fmaf(a2.w, r2.w, s);
    return s;
}

__device__ __forceinline__ float halfsum(float s) {
    s += __shfl_xor_sync(0xffffffffu, s, 8);
    s += __shfl_xor_sync(0xffffffffu, s, 4);
    s += __shfl_xor_sync(0xffffffffu, s, 2);
    s += __shfl_xor_sync(0xffffffffu, s, 1);
    return s;
}

__device__ __forceinline__ int reflect128(int t) {
    if (t < 0) t = -t;
    if (t > 127) t = 254 - t;
    return t;
}

// Score a pair of candidates (one per half-warp) and fold into (best,bestc)
// in index order jA then jA+1 (strict > == first-occurrence argmax).
__device__ __forceinline__ void score_pair(float4 a0, float4 a1, float4 a2, int l,
                                           int h, int cc, float& best, int& bestc) {
    float s = halfsum(dot48h(a0, a1, a2, g_ref_t4 + (size_t)cc * NF4 + l));
    float sO = __shfl_xor_sync(0xffffffffu, s, 16);
    int   cO = __shfl_xor_sync(0xffffffffu, cc, 16);
    float s0 = h ? sO : s;  int c0 = h ? cO : cc;
    float s1 = h ? s : sO;  int c1 = h ? cc : cO;
    if (s0 > best) { best = s0; bestc = c0; }
    if (s1 > best) { best = s1; bestc = c1; }
}

// One propagation step given preloaded input regs; returns updated (myc, sc).
__device__ __forceinline__ void prop_step(float4 a0, float4 a1, float4 a2,
                                          int l, int h, int p, int k,
                                          const int* __restrict__ cb,
                                          int& myc, float& sc) {
    int y = p >> 7, x = p & 127;
    auto coord_at = [&](int j) {
        int ny = reflect128(y + k * (j / 3 - 1));
        int nx = reflect128(x + k * (j % 3 - 1));
        return cb[(ny << 7) + nx];
    };
    float best = -3.4e38f; int bestc = 0;
    score_pair(a0, a1, a2, l, h, coord_at(0 + h), best, bestc);
    score_pair(a0, a1, a2, l, h, coord_at(2 + h), best, bestc);
    if (sc > best) { best = sc; bestc = myc; }
    score_pair(a0, a1, a2, l, h, coord_at(5 + h), best, bestc);
    score_pair(a0, a1, a2, l, h, coord_at(7 + h), best, bestc);
    myc = bestc; sc = best;
}

// ---------------------------------------------------------------------------
// Step 0 (prop, k=1) with init fused: neighbor coords straight from inref_x/y;
// center score computed as a 9th dot. Everything after PDL wait (reads
// transpose output).
__global__ __launch_bounds__(256) void prop_first_kernel(
    const float* __restrict__ inref_x, const float* __restrict__ inref_y) {
    PDL_SIGNAL();
    PDL_WAIT();
    int warp = blockIdx.x * 8 + (threadIdx.x >> 5);
    int lane = threadIdx.x & 31;
    int h = lane >> 4, l = lane & 15;
    int p = warp;
    int y = p >> 7, x = p & 127;

    const float4* __restrict__ a4 = g_in_t4 + (size_t)p * NF4 + l;
    float4 a0 = a4[0], a1 = a4[16], a2 = a4[32];

    auto coord_at = [&](int j) {
        int ny = reflect128(y + (j / 3 - 1));
        int nx = reflect128(x + (j % 3 - 1));
        int np = (ny << 7) + nx;
        return ((int)inref_y[np] << 7) + (int)inref_x[np];
    };

    float best = -3.4e38f; int bestc = 0;
    score_pair(a0, a1, a2, l, h, coord_at(0 + h), best, bestc);
    score_pair(a0, a1, a2, l, h, coord_at(2 + h), best, bestc);
    {   // center candidate j=4
        int cc4 = ((int)inref_y[p] << 7) + (int)inref_x[p];
        float s4 = halfsum(dot48h(a0, a1, a2, g_ref_t4 + (size_t)cc4 * NF4 + l));
        if (s4 > best) { best = s4; bestc = cc4; }
    }
    score_pair(a0, a1, a2, l, h, coord_at(5 + h), best, bestc);
    score_pair(a0, a1, a2, l, h, coord_at(7 + h), best, bestc);

    if (lane == 0) { g_coord[0][p] = bestc; g_score[p] = best; }
}

// ---------------------------------------------------------------------------
// Propagation step (k >= 2). Early phase: input loads (static data) overlap
// the predecessor's tail; wait gates the coord/score reads.
__global__ __launch_bounds__(256) void prop_kernel(int k, int cur, int nxt) {
    PDL_SIGNAL();
    int warp = blockIdx.x * 8 + (threadIdx.x >> 5);
    int lane = threadIdx.x & 31;
    int h = lane >> 4, l = lane & 15;
    int p = warp;

    const float4* __restrict__ a4 = g_in_t4 + (size_t)p * NF4 + l;
    float4 a0 = a4[0], a1 = a4[16], a2 = a4[32];

    PDL_WAIT();
    const int* __restrict__ cb = g_coord[cur];
    int myc = cb[p];
    float sc = g_score[p];

    prop_step(a0, a1, a2, l, h, p, k, cb, myc, sc);

    if (lane == 0) { g_coord[nxt][p] = myc; g_score[p] = sc; }
}

// ---------------------------------------------------------------------------
// Fused: one prop step (k=64) + 7 random-search steps (k=1..64), state in
// registers. Writes the OTHER coord buffer (concurrent readers of cur exist).
// FINAL=1 writes the kernel output instead.
template <int FINAL>
__global__ __launch_bounds__(256) void rand7_kernel(int prop_iter, int cur,
                                                    float* __restrict__ out,
                                                    int out_size) {
    PDL_SIGNAL();
    int warp = blockIdx.x * 8 + (threadIdx.x >> 5);
    int lane = threadIdx.x & 31;
    int h = lane >> 4, l = lane & 15;
    int p = warp;

    const float4* __restrict__ a4 = g_in_t4 + (size_t)p * NF4 + l;
    float4 a0 = a4[0], a1 = a4[16], a2 = a4[32];

    PDL_WAIT();
    const int* __restrict__ cb = g_coord[cur];
    int myc = cb[p];
    float sc = g_score[p];

    // trailing propagation step of this half-iteration (k = 64)
    prop_step(a0, a1, a2, l, h, p, 64, cb, myc, sc);

    // 7 random-search steps, pixel-local
#pragma unroll
    for (int t = 0; t < 7; t++) {
        const int k = 1 << t;
        const int m = prop_iter & (k - 1);       // prop_iter % k
        int x0 = myc & 127, y0 = myc >> 7;

        auto coord_at = [&](int j) {
            int cx = (x0 + k * (j % 3 - 1) + m * c_DX[j] + 128) & 127;
            int cy = (y0 + k * (j / 3 - 1) + m * c_DY[j] + 128) & 127;
            return (cy << 7) | cx;
        };

        float best = -3.4e38f; int bestc = 0;
        score_pair(a0, a1, a2, l, h, coord_at(0 + h), best, bestc);
        score_pair(a0, a1, a2, l, h, coord_at(2 + h), best, bestc);
        if (sc > best) { best = sc; bestc = myc; }
        score_pair(a0, a1, a2, l, h, coord_at(5 + h), best, bestc);
        score_pair(a0, a1, a2, l, h, coord_at(7 + h), best, bestc);
        myc = bestc; sc = best;
    }

    if (FINAL) {
        if (lane == 0) {
            if (p < out_size)        out[p] = (float)myc;
            if (NPIX + p < out_size) out[NPIX + p] = sc;
        }
    } else {
        if (lane == 0) { g_coord[cur ^ 1][p] = myc; g_score[p] = sc; }
    }
}

// ---------------------------------------------------------------------------
template <typename K, typename... Args>
static void pdl_launch(K kern, dim3 g, dim3 b, Args... args) {
    cudaLaunchConfig_t cfg = {};
    cfg.gridDim = g;
    cfg.blockDim = b;
    cfg.stream = 0;   // legacy default stream (same as <<<>>>)
    cudaLaunchAttribute attr[1];
    attr[0].id = cudaLaunchAttributeProgrammaticStreamSerialization;
    attr[0].val.programmaticStreamSerializationAllowed = 1;
    cfg.attrs = attr;
    cfg.numAttrs = 1;
    cudaLaunchKernelEx(&cfg, kern, args...);
}

extern "C" void kernel_launch(void* const* d_in, const int* in_sizes, int n_in,
                              void* d_out, int out_size) {
    const float* input_map = (const float*)d_in[0];
    const float* ref_map   = (const float*)d_in[1];
    const float* inref_x   = (const float*)d_in[2];
    const float* inref_y   = (const float*)d_in[3];

    dim3 tb(32, 32);
    dim3 tg(NPIX / 32, C / 32, 2);
    transpose_kernel<<<tg, tb>>>(input_map, ref_map);

    const dim3 grid(NPIX / 8);   // warp per pixel, 8 warps per 256-thread block
    const dim3 blk(256);

    // Iteration 0: prop k=1 (init fused), k=2..32, then rand7A (prop64 + rand).
    pdl_launch(prop_first_kernel, grid, blk, inref_x, inref_y);
    int cur = 0;
    for (int k = 2; k <= 32; k *= 2) {
        pdl_launch(prop_kernel, grid, blk, k, cur, cur ^ 1);
        cur ^= 1;
    }
    pdl_launch(rand7_kernel<0>, grid, blk, 0, cur, (float*)nullptr, 0);
    cur ^= 1;

    // Iteration 1: prop k=1..32, then rand7B (prop64 + rand + output).
    for (int k = 1; k <= 32; k *= 2) {
        pdl_launch(prop_kernel, grid, blk, k, cur, cur ^ 1);
        cur ^= 1;
    }
    pdl_launch(rand7_kernel<1>, grid, blk, 1, cur, (float*)d_out, out_size);
}

// round 10
// speedup vs baseline: 2.1881x; 1.0579x over previous
#include <cuda_runtime.h>
#include <cuda_bf16.h>

// PatchMatch (b=1, c=192, h=w=128); fixed: iteration_count=2, minWH=127, is_final=1.
// Launch plan (15 kernels, PDL overlap on all eval->eval edges):
//   transpose | prop_first(k=1,init) prop(2..32)x5 rand7A(prop64+7 rand)
//             | prop(1..32)x6 rand7B(prop64+7 rand+output)

#define C 192
#define NF4 48          // 192 floats = 48 float4
#define H 128
#define W 128
#define NPIX (H * W)

#define PDL_SIGNAL() asm volatile("griddepcontrol.launch_dependents;")
#define PDL_WAIT()   asm volatile("griddepcontrol.wait;" ::: "memory")

__device__ float4 g_in_t4[NPIX * NF4];    // pixel-major input  [p][48]
__device__ float4 g_ref_t4[NPIX * NF4];   // pixel-major ref    [p][48]
__device__ int    g_coord[2][NPIX];       // packed y*128+x, double-buffered
__device__ float  g_score[NPIX];          // score of current coord

__constant__ int c_DX[9] = {0, -1, -1, 0, 0, 0, 1, 1, 0};
__constant__ int c_DY[9] = {1, 0, 0, 1, 0, -1, 0, 0, -1};

// ---------------------------------------------------------------------------
// Vectorized transpose [C][NPIX] -> [NPIX][C]. Tile: 32 channels x 128 pixels.
// 256 threads, 4 float4 reads + 4 float4 writes per thread, all coalesced,
// smem phases conflict-free (pad 129).
__global__ __launch_bounds__(256) void transpose_kernel(
    const float* __restrict__ in0, const float* __restrict__ in1) {
    __shared__ float tile[32][129];
    const float* in = blockIdx.z ? in1 : in0;
    float* out = blockIdx.z ? (float*)g_ref_t4 : (float*)g_in_t4;
    int p0 = blockIdx.x * 128;   // pixel tile
    int c0 = blockIdx.y * 32;    // channel tile
    int tid = threadIdx.x;

    // Read: 4 passes of 8 channel-rows; 32 float4 along pixels per row.
#pragma unroll
    for (int pass = 0; pass < 4; pass++) {
        int r = pass * 8 + (tid >> 5);
        int p4 = tid & 31;
        const float4* inv = (const float4*)(in + (size_t)(c0 + r) * NPIX + p0);
        float4 v = inv[p4];
        tile[r][4 * p4 + 0] = v.x;
        tile[r][4 * p4 + 1] = v.y;
        tile[r][4 * p4 + 2] = v.z;
        tile[r][4 * p4 + 3] = v.w;
    }
    __syncthreads();

    // Write: 4 passes of 32 pixels; 8 float4 (32 channels) per pixel.
#pragma unroll
    for (int pass = 0; pass < 4; pass++) {
        int pix = pass * 32 + (tid >> 3);
        int c4 = tid & 7;
        float4 w;
        w.x = tile[4 * c4 + 0][pix];
        w.y = tile[4 * c4 + 1][pix];
        w.z = tile[4 * c4 + 2][pix];
        w.w = tile[4 * c4 + 3][pix];
        float4* outv = (float4*)(out + (size_t)(p0 + pix) * C + c0);
        outv[c4] = w;
    }
}

// ---------------------------------------------------------------------------
// Canonical per-lane (l in [0,16)) partial dot; identical everywhere so equal
// coords give bit-identical scores. r4 is pre-offset by l.
__device__ __forceinline__ float dot48h(float4 a0, float4 a1, float4 a2,
                                        const float4* __restrict__ r4) {
    float4 r0 = r4[0], r1 = r4[16], r2 = r4[32];
    float s;
    s = a0.x * r0.x;          s = fmaf(a0.y, r0.y, s);
    s = fmaf(a0.z, r0.z, s);  s = fmaf(a0.w, r0.w, s);
    s = fmaf(a1.x, r1.x, s);  s = fmaf(a1.y, r1.y, s);
    s = fmaf(a1.z, r1.z, s);  s = fmaf(a1.w, r1.w, s);
    s = fmaf(a2.x, r2.x, s);  s = fmaf(a2.y, r2.y, s);
    s = fmaf(a2.z, r2.z, s);  s = fmaf(a2.w, r2.w, s);
    return s;
}

__device__ __forceinline__ float halfsum(float s) {
    s += __shfl_xor_sync(0xffffffffu, s, 8);
    s += __shfl_xor_sync(0xffffffffu, s, 4);
    s += __shfl_xor_sync(0xffffffffu, s, 2);
    s += __shfl_xor_sync(0xffffffffu, s, 1);
    return s;
}

__device__ __forceinline__ int reflect128(int t) {
    if (t < 0) t = -t;
    if (t > 127) t = 254 - t;
    return t;
}

// Score a pair of candidates (one per half-warp) and fold into (best,bestc)
// in index order jA then jA+1 (strict > == first-occurrence argmax).
__device__ __forceinline__ void score_pair(float4 a0, float4 a1, float4 a2, int l,
                                           int h, int cc, float& best, int& bestc) {
    float s = halfsum(dot48h(a0, a1, a2, g_ref_t4 + (size_t)cc * NF4 + l));
    float sO = __shfl_xor_sync(0xffffffffu, s, 16);
    int   cO = __shfl_xor_sync(0xffffffffu, cc, 16);
    float s0 = h ? sO : s;  int c0 = h ? cO : cc;
    float s1 = h ? s : sO;  int c1 = h ? cc : cO;
    if (s0 > best) { best = s0; bestc = c0; }
    if (s1 > best) { best = s1; bestc = c1; }
}

// One propagation step given preloaded input regs; returns updated (myc, sc).
__device__ __forceinline__ void prop_step(float4 a0, float4 a1, float4 a2,
                                          int l, int h, int p, int k,
                                          const int* __restrict__ cb,
                                          int& myc, float& sc) {
    int y = p >> 7, x = p & 127;
    auto coord_at = [&](int j) {
        int ny = reflect128(y + k * (j / 3 - 1));
        int nx = reflect128(x + k * (j % 3 - 1));
        return cb[(ny << 7) + nx];
    };
    float best = -3.4e38f; int bestc = 0;
    score_pair(a0, a1, a2, l, h, coord_at(0 + h), best, bestc);
    score_pair(a0, a1, a2, l, h, coord_at(2 + h), best, bestc);
    if (sc > best) { best = sc; bestc = myc; }
    score_pair(a0, a1, a2, l, h, coord_at(5 + h), best, bestc);
    score_pair(a0, a1, a2, l, h, coord_at(7 + h), best, bestc);
    myc = bestc; sc = best;
}

// ---------------------------------------------------------------------------
// Step 0 (prop, k=1) with init fused: neighbor coords straight from inref_x/y;
// center score computed as a 9th dot. Everything after PDL wait (reads
// transpose output).
__global__ __launch_bounds__(256) void prop_first_kernel(
    const float* __restrict__ inref_x, const float* __restrict__ inref_y) {
    PDL_SIGNAL();
    PDL_WAIT();
    int warp = blockIdx.x * 8 + (threadIdx.x >> 5);
    int lane = threadIdx.x & 31;
    int h = lane >> 4, l = lane & 15;
    int p = warp;
    int y = p >> 7, x = p & 127;

    const float4* __restrict__ a4 = g_in_t4 + (size_t)p * NF4 + l;
    float4 a0 = a4[0], a1 = a4[16], a2 = a4[32];

    auto coord_at = [&](int j) {
        int ny = reflect128(y + (j / 3 - 1));
        int nx = reflect128(x + (j % 3 - 1));
        int np = (ny << 7) + nx;
        return ((int)inref_y[np] << 7) + (int)inref_x[np];
    };

    float best = -3.4e38f; int bestc = 0;
    score_pair(a0, a1, a2, l, h, coord_at(0 + h), best, bestc);
    score_pair(a0, a1, a2, l, h, coord_at(2 + h), best, bestc);
    {   // center candidate j=4
        int cc4 = ((int)inref_y[p] << 7) + (int)inref_x[p];
        float s4 = halfsum(dot48h(a0, a1, a2, g_ref_t4 + (size_t)cc4 * NF4 + l));
        if (s4 > best) { best = s4; bestc = cc4; }
    }
    score_pair(a0, a1, a2, l, h, coord_at(5 + h), best, bestc);
    score_pair(a0, a1, a2, l, h, coord_at(7 + h), best, bestc);

    if (lane == 0) { g_coord[0][p] = bestc; g_score[p] = best; }
}

// ---------------------------------------------------------------------------
// Propagation step (k >= 2). Early phase: input loads (static data) overlap
// the predecessor's tail; wait gates the coord/score reads. Reg cap -> occ.
__global__ __launch_bounds__(256, 5) void prop_kernel(int k, int cur, int nxt) {
    PDL_SIGNAL();
    int warp = blockIdx.x * 8 + (threadIdx.x >> 5);
    int lane = threadIdx.x & 31;
    int h = lane >> 4, l = lane & 15;
    int p = warp;

    const float4* __restrict__ a4 = g_in_t4 + (size_t)p * NF4 + l;
    float4 a0 = a4[0], a1 = a4[16], a2 = a4[32];

    PDL_WAIT();
    const int* __restrict__ cb = g_coord[cur];
    int myc = cb[p];
    float sc = g_score[p];

    prop_step(a0, a1, a2, l, h, p, k, cb, myc, sc);

    if (lane == 0) { g_coord[nxt][p] = myc; g_score[p] = sc; }
}

// ---------------------------------------------------------------------------
// Fused: one prop step (k=64) + 7 random-search steps (k=1..64), state in
// registers. Writes the OTHER coord buffer (concurrent readers of cur exist).
// FINAL=1 writes the kernel output instead.
template <int FINAL>
__global__ __launch_bounds__(256) void rand7_kernel(int prop_iter, int cur,
                                                    float* __restrict__ out,
                                                    int out_size) {
    PDL_SIGNAL();
    int warp = blockIdx.x * 8 + (threadIdx.x >> 5);
    int lane = threadIdx.x & 31;
    int h = lane >> 4, l = lane & 15;
    int p = warp;

    const float4* __restrict__ a4 = g_in_t4 + (size_t)p * NF4 + l;
    float4 a0 = a4[0], a1 = a4[16], a2 = a4[32];

    PDL_WAIT();
    const int* __restrict__ cb = g_coord[cur];
    int myc = cb[p];
    float sc = g_score[p];

    // trailing propagation step of this half-iteration (k = 64)
    prop_step(a0, a1, a2, l, h, p, 64, cb, myc, sc);

    // 7 random-search steps, pixel-local
#pragma unroll
    for (int t = 0; t < 7; t++) {
        const int k = 1 << t;
        const int m = prop_iter & (k - 1);       // prop_iter % k
        int x0 = myc & 127, y0 = myc >> 7;

        auto coord_at = [&](int j) {
            int cx = (x0 + k * (j % 3 - 1) + m * c_DX[j] + 128) & 127;
            int cy = (y0 + k * (j / 3 - 1) + m * c_DY[j] + 128) & 127;
            return (cy << 7) | cx;
        };

        float best = -3.4e38f; int bestc = 0;
        score_pair(a0, a1, a2, l, h, coord_at(0 + h), best, bestc);
        score_pair(a0, a1, a2, l, h, coord_at(2 + h), best, bestc);
        if (sc > best) { best = sc; bestc = myc; }
        score_pair(a0, a1, a2, l, h, coord_at(5 + h), best, bestc);
        score_pair(a0, a1, a2, l, h, coord_at(7 + h), best, bestc);
        myc = bestc; sc = best;
    }

    if (FINAL) {
        if (lane == 0) {
            if (p < out_size)        out[p] = (float)myc;
            if (NPIX + p < out_size) out[NPIX + p] = sc;
        }
    } else {
        if (lane == 0) { g_coord[cur ^ 1][p] = myc; g_score[p] = sc; }
    }
}

// ---------------------------------------------------------------------------
template <typename K, typename... Args>
static void pdl_launch(K kern, dim3 g, dim3 b, Args... args) {
    cudaLaunchConfig_t cfg = {};
    cfg.gridDim = g;
    cfg.blockDim = b;
    cfg.stream = 0;   // legacy default stream (same as <<<>>>)
    cudaLaunchAttribute attr[1];
    attr[0].id = cudaLaunchAttributeProgrammaticStreamSerialization;
    attr[0].val.programmaticStreamSerializationAllowed = 1;
    cfg.attrs = attr;
    cfg.numAttrs = 1;
    cudaLaunchKernelEx(&cfg, kern, args...);
}

extern "C" void kernel_launch(void* const* d_in, const int* in_sizes, int n_in,
                              void* d_out, int out_size) {
    const float* input_map = (const float*)d_in[0];
    const float* ref_map   = (const float*)d_in[1];
    const float* inref_x   = (const float*)d_in[2];
    const float* inref_y   = (const float*)d_in[3];

    dim3 tg(NPIX / 128, C / 32, 2);
    transpose_kernel<<<tg, 256>>>(input_map, ref_map);

    const dim3 grid(NPIX / 8);   // warp per pixel, 8 warps per 256-thread block
    const dim3 blk(256);

    // Iteration 0: prop k=1 (init fused), k=2..32, then rand7A (prop64 + rand).
    pdl_launch(prop_first_kernel, grid, blk, inref_x, inref_y);
    int cur = 0;
    for (int k = 2; k <= 32; k *= 2) {
        pdl_launch(prop_kernel, grid, blk, k, cur, cur ^ 1);
        cur ^= 1;
    }
    pdl_launch(rand7_kernel<0>, grid, blk, 0, cur, (float*)nullptr, 0);
    cur ^= 1;

    // Iteration 1: prop k=1..32, then rand7B (prop64 + rand + output).
    for (int k = 1; k <= 32; k *= 2) {
        pdl_launch(prop_kernel, grid, blk, k, cur, cur ^ 1);
        cur ^= 1;
    }
    pdl_launch(rand7_kernel<1>, grid, blk, 1, cur, (float*)d_out, out_size);
}

// round 11
// speedup vs baseline: 2.2490x; 1.0278x over previous
#include <cuda_runtime.h>
#include <cuda_bf16.h>

// PatchMatch (b=1, c=192, h=w=128); fixed: iteration_count=2, minWH=127, is_final=1.
// Launch plan (15 kernels, PDL overlap on all eval->eval edges):
//   transpose | prop_first(k=1,init) prop(2..32)x5 rand7A(prop64+7 rand)
//             | prop(1..32)x6 rand7B(prop64+7 rand+output)
// State = int2 {coord, score bits}, double-buffered. Candidate-coord gathers
// hoisted ahead of the score pipeline (they were the prop critical path).

#define C 192
#define NF4 48          // 192 floats = 48 float4
#define H 128
#define W 128
#define NPIX (H * W)

#define PDL_SIGNAL() asm volatile("griddepcontrol.launch_dependents;")
#define PDL_WAIT()   asm volatile("griddepcontrol.wait;" ::: "memory")

__device__ float4 g_in_t4[NPIX * NF4];    // pixel-major input  [p][48]
__device__ float4 g_ref_t4[NPIX * NF4];   // pixel-major ref    [p][48]
__device__ int2   g_state[2][NPIX];       // {packed y*128+x, float bits of score}

__constant__ int c_DX[9] = {0, -1, -1, 0, 0, 0, 1, 1, 0};
__constant__ int c_DY[9] = {1, 0, 0, 1, 0, -1, 0, 0, -1};

// ---------------------------------------------------------------------------
// Vectorized transpose [C][NPIX] -> [NPIX][C]. Tile: 32 channels x 128 pixels.
__global__ __launch_bounds__(256) void transpose_kernel(
    const float* __restrict__ in0, const float* __restrict__ in1) {
    __shared__ float tile[32][129];
    const float* in = blockIdx.z ? in1 : in0;
    float* out = blockIdx.z ? (float*)g_ref_t4 : (float*)g_in_t4;
    int p0 = blockIdx.x * 128;
    int c0 = blockIdx.y * 32;
    int tid = threadIdx.x;

#pragma unroll
    for (int pass = 0; pass < 4; pass++) {
        int r = pass * 8 + (tid >> 5);
        int p4 = tid & 31;
        const float4* inv = (const float4*)(in + (size_t)(c0 + r) * NPIX + p0);
        float4 v = inv[p4];
        tile[r][4 * p4 + 0] = v.x;
        tile[r][4 * p4 + 1] = v.y;
        tile[r][4 * p4 + 2] = v.z;
        tile[r][4 * p4 + 3] = v.w;
    }
    __syncthreads();

#pragma unroll
    for (int pass = 0; pass < 4; pass++) {
        int pix = pass * 32 + (tid >> 3);
        int c4 = tid & 7;
        float4 w;
        w.x = tile[4 * c4 + 0][pix];
        w.y = tile[4 * c4 + 1][pix];
        w.z = tile[4 * c4 + 2][pix];
        w.w = tile[4 * c4 + 3][pix];
        float4* outv = (float4*)(out + (size_t)(p0 + pix) * C + c0);
        outv[c4] = w;
    }
}

// ---------------------------------------------------------------------------
// Canonical per-lane (l in [0,16)) partial dot; identical everywhere so equal
// coords give bit-identical scores. r4 is pre-offset by l.
__device__ __forceinline__ float dot48h(float4 a0, float4 a1, float4 a2,
                                        const float4* __restrict__ r4) {
    float4 r0 = r4[0], r1 = r4[16], r2 = r4[32];
    float s;
    s = a0.x * r0.x;          s = fmaf(a0.y, r0.y, s);
    s = fmaf(a0.z, r0.z, s);  s = fmaf(a0.w, r0.w, s);
    s = fmaf(a1.x, r1.x, s);  s = fmaf(a1.y, r1.y, s);
    s = fmaf(a1.z, r1.z, s);  s = fmaf(a1.w, r1.w, s);
    s = fmaf(a2.x, r2.x, s);  s = fmaf(a2.y, r2.y, s);
    s = fmaf(a2.z, r2.z, s);  s = fmaf(a2.w, r2.w, s);
    return s;
}

__device__ __forceinline__ float halfsum(float s) {
    s += __shfl_xor_sync(0xffffffffu, s, 8);
    s += __shfl_xor_sync(0xffffffffu, s, 4);
    s += __shfl_xor_sync(0xffffffffu, s, 2);
    s += __shfl_xor_sync(0xffffffffu, s, 1);
    return s;
}

__device__ __forceinline__ int reflect128(int t) {
    if (t < 0) t = -t;
    if (t > 127) t = 254 - t;
    return t;
}

// Score a pair of candidates (this half's cc; other half's via shuffle) and
// fold in index order jA then jA+1 (strict > == first-occurrence argmax).
__device__ __forceinline__ void score_pair(float4 a0, float4 a1, float4 a2, int l,
                                           int h, int cc, float& best, int& bestc) {
    float s = halfsum(dot48h(a0, a1, a2, g_ref_t4 + (size_t)cc * NF4 + l));
    float sO = __shfl_xor_sync(0xffffffffu, s, 16);
    int   cO = __shfl_xor_sync(0xffffffffu, cc, 16);
    float s0 = h ? sO : s;  int c0 = h ? cO : cc;
    float s1 = h ? s : sO;  int c1 = h ? cc : cO;
    if (s0 > best) { best = s0; bestc = c0; }
    if (s1 > best) { best = s1; bestc = c1; }
}

// One propagation step with PRE-FETCHED candidate coords cands[4]
// (this half's candidates j = {0,2,5,7}+h). Updates (myc, sc).
__device__ __forceinline__ void prop_core(float4 a0, float4 a1, float4 a2,
                                          int l, int h, const int* cands,
                                          int& myc, float& sc) {
    float best = -3.4e38f; int bestc = 0;
    score_pair(a0, a1, a2, l, h, cands[0], best, bestc);
    score_pair(a0, a1, a2, l, h, cands[1], best, bestc);
    if (sc > best) { best = sc; bestc = myc; }
    score_pair(a0, a1, a2, l, h, cands[2], best, bestc);
    score_pair(a0, a1, a2, l, h, cands[3], best, bestc);
    myc = bestc; sc = best;
}

// Gather the 4 per-half candidate coords for a prop step (all loads
// independent -> in flight concurrently).
__device__ __forceinline__ void gather_cands(const int2* __restrict__ sb,
                                             int p, int k, int h, int* cands) {
    const int jb[4] = {0, 2, 5, 7};
    int y = p >> 7, x = p & 127;
#pragma unroll
    for (int i = 0; i < 4; i++) {
        int j = jb[i] + h;
        int ny = reflect128(y + k * (j / 3 - 1));
        int nx = reflect128(x + k * (j % 3 - 1));
        cands[i] = ((const int*)sb)[2 * ((ny << 7) + nx)];   // coord word only
    }
}

// ---------------------------------------------------------------------------
// Step 0 (prop, k=1) with init fused: neighbor coords straight from inref_x/y;
// center score computed as a 9th dot.
__global__ __launch_bounds__(256) void prop_first_kernel(
    const float* __restrict__ inref_x, const float* __restrict__ inref_y) {
    PDL_SIGNAL();
    PDL_WAIT();
    int warp = blockIdx.x * 8 + (threadIdx.x >> 5);
    int lane = threadIdx.x & 31;
    int h = lane >> 4, l = lane & 15;
    int p = warp;
    int y = p >> 7, x = p & 127;

    const float4* __restrict__ a4 = g_in_t4 + (size_t)p * NF4 + l;
    float4 a0 = a4[0], a1 = a4[16], a2 = a4[32];

    // Pre-fetch all candidate coords (independent loads).
    const int jb[4] = {0, 2, 5, 7};
    int cands[4];
#pragma unroll
    for (int i = 0; i < 4; i++) {
        int j = jb[i] + h;
        int ny = reflect128(y + (j / 3 - 1));
        int nx = reflect128(x + (j % 3 - 1));
        int np = (ny << 7) + nx;
        cands[i] = ((int)inref_y[np] << 7) + (int)inref_x[np];
    }
    int cc4 = ((int)inref_y[p] << 7) + (int)inref_x[p];

    float best = -3.4e38f; int bestc = 0;
    score_pair(a0, a1, a2, l, h, cands[0], best, bestc);
    score_pair(a0, a1, a2, l, h, cands[1], best, bestc);
    {   // center candidate j=4
        float s4 = halfsum(dot48h(a0, a1, a2, g_ref_t4 + (size_t)cc4 * NF4 + l));
        if (s4 > best) { best = s4; bestc = cc4; }
    }
    score_pair(a0, a1, a2, l, h, cands[2], best, bestc);
    score_pair(a0, a1, a2, l, h, cands[3], best, bestc);

    if (lane == 0) g_state[0][p] = make_int2(bestc, __float_as_int(best));
}

// ---------------------------------------------------------------------------
// Propagation step (k >= 2). Input loads overlap predecessor tail via PDL;
// coord gathers hoisted ahead of the score pipeline.
__global__ __launch_bounds__(256, 5) void prop_kernel(int k, int cur, int nxt) {
    PDL_SIGNAL();
    int warp = blockIdx.x * 8 + (threadIdx.x >> 5);
    int lane = threadIdx.x & 31;
    int h = lane >> 4, l = lane & 15;
    int p = warp;

    const float4* __restrict__ a4 = g_in_t4 + (size_t)p * NF4 + l;
    float4 a0 = a4[0], a1 = a4[16], a2 = a4[32];

    PDL_WAIT();
    const int2* __restrict__ sb = g_state[cur];
    int2 st = sb[p];
    int cands[4];
    gather_cands(sb, p, k, h, cands);
    int myc = st.x;
    float sc = __int_as_float(st.y);

    prop_core(a0, a1, a2, l, h, cands, myc, sc);

    if (lane == 0) g_state[nxt][p] = make_int2(myc, __float_as_int(sc));
}

// ---------------------------------------------------------------------------
// Fused: one prop step (k=64) + 7 random-search steps (k=1..64), state in
// registers. Writes the OTHER state buffer (concurrent readers of cur exist).
// FINAL=1 writes the kernel output instead.
template <int FINAL>
__global__ __launch_bounds__(256) void rand7_kernel(int prop_iter, int cur,
                                                    float* __restrict__ out,
                                                    int out_size) {
    PDL_SIGNAL();
    int warp = blockIdx.x * 8 + (threadIdx.x >> 5);
    int lane = threadIdx.x & 31;
    int h = lane >> 4, l = lane & 15;
    int p = warp;

    const float4* __restrict__ a4 = g_in_t4 + (size_t)p * NF4 + l;
    float4 a0 = a4[0], a1 = a4[16], a2 = a4[32];

    PDL_WAIT();
    const int2* __restrict__ sb = g_state[cur];
    int2 st = sb[p];
    int cands[4];
    gather_cands(sb, p, 64, h, cands);        // trailing prop step, k = 64
    int myc = st.x;
    float sc = __int_as_float(st.y);

    prop_core(a0, a1, a2, l, h, cands, myc, sc);

    // 7 random-search steps, pixel-local (coords arithmetic, no gathers)
#pragma unroll
    for (int t = 0; t < 7; t++) {
        const int k = 1 << t;
        const int m = prop_iter & (k - 1);       // prop_iter % k
        int x0 = myc & 127, y0 = myc >> 7;

        auto coord_at = [&](int j) {
            int cx = (x0 + k * (j % 3 - 1) + m * c_DX[j] + 128) & 127;
            int cy = (y0 + k * (j / 3 - 1) + m * c_DY[j] + 128) & 127;
            return (cy << 7) | cx;
        };

        float best = -3.4e38f; int bestc = 0;
        score_pair(a0, a1, a2, l, h, coord_at(0 + h), best, bestc);
        score_pair(a0, a1, a2, l, h, coord_at(2 + h), best, bestc);
        if (sc > best) { best = sc; bestc = myc; }
        score_pair(a0, a1, a2, l, h, coord_at(5 + h), best, bestc);
        score_pair(a0, a1, a2, l, h, coord_at(7 + h), best, bestc);
        myc = bestc; sc = best;
    }

    if (FINAL) {
        if (lane == 0) {
            if (p < out_size)        out[p] = (float)myc;
            if (NPIX + p < out_size) out[NPIX + p] = sc;
        }
    } else {
        if (lane == 0) g_state[cur ^ 1][p] = make_int2(myc, __float_as_int(sc));
    }
}

// ---------------------------------------------------------------------------
template <typename K, typename... Args>
static void pdl_launch(K kern, dim3 g, dim3 b, Args... args) {
    cudaLaunchConfig_t cfg = {};
    cfg.gridDim = g;
    cfg.blockDim = b;
    cfg.stream = 0;   // legacy default stream (same as <<<>>>)
    cudaLaunchAttribute attr[1];
    attr[0].id = cudaLaunchAttributeProgrammaticStreamSerialization;
    attr[0].val.programmaticStreamSerializationAllowed = 1;
    cfg.attrs = attr;
    cfg.numAttrs = 1;
    cudaLaunchKernelEx(&cfg, kern, args...);
}

extern "C" void kernel_launch(void* const* d_in, const int* in_sizes, int n_in,
                              void* d_out, int out_size) {
    const float* input_map = (const float*)d_in[0];
    const float* ref_map   = (const float*)d_in[1];
    const float* inref_x   = (const float*)d_in[2];
    const float* inref_y   = (const float*)d_in[3];

    dim3 tg(NPIX / 128, C / 32, 2);
    transpose_kernel<<<tg, 256>>>(input_map, ref_map);

    const dim3 grid(NPIX / 8);   // warp per pixel, 8 warps per 256-thread block
    const dim3 blk(256);

    // Iteration 0: prop k=1 (init fused), k=2..32, then rand7A (prop64 + rand).
    pdl_launch(prop_first_kernel, grid, blk, inref_x, inref_y);
    int cur = 0;
    for (int k = 2; k <= 32; k *= 2) {
        pdl_launch(prop_kernel, grid, blk, k, cur, cur ^ 1);
        cur ^= 1;
    }
    pdl_launch(rand7_kernel<0>, grid, blk, 0, cur, (float*)nullptr, 0);
    cur ^= 1;

    // Iteration 1: prop k=1..32, then rand7B (prop64 + rand + output).
    for (int k = 1; k <= 32; k *= 2) {
        pdl_launch(prop_kernel, grid, blk, k, cur, cur ^ 1);
        cur ^= 1;
    }
    pdl_launch(rand7_kernel<1>, grid, blk, 1, cur, (float*)d_out, out_size);
}